// round 2
// baseline (speedup 1.0000x reference)
#include <cuda_runtime.h>
#include <math.h>
#include <stdint.h>

#define BB 8
#define NN 2048
#define FIN 256
#define FOUT 128
#define ALPHA 0.2f
#define CUTOFF 0.1f
#define NEGINF -9e15f

#define QT 64
#define KT 64
#define PS2 66   // p-tile row stride in uint64 units (duplicated pairs), 16B-aligned

// Scratch (no cudaMalloc allowed)
__device__ float g_h[BB * NN * FOUT];   // 8 MB
__device__ float g_fs[BB * NN];
__device__ float g_fd[BB * NN];
__device__ float g_fdmax[BB];

#define FFMA2(acc, a, b) \
    asm("fma.rn.f32x2 %0, %1, %2, %0;" : "+l"(acc) : "l"(a), "l"(b))

// ---------------------------------------------------------------------------
// Kernel 1: h = x @ W (M=16384, K=256, N=128) with f32x2 accumulation.
// Fused f_src = h@a[:128], f_dst = h@a[128:].
// ---------------------------------------------------------------------------
__global__ __launch_bounds__(256, 2)
void gemm_h_kernel(const float* __restrict__ x, const float* __restrict__ W,
                   const float* __restrict__ a) {
    __shared__ float xs[64 * 33];
    __shared__ float ws[32 * 128];

    const int t  = threadIdx.x;
    const int tx = t & 31;            // cols tx*4..tx*4+3
    const int ty = t >> 5;            // rows ty*8..ty*8+7
    const int row0 = blockIdx.x * 64;

    uint64_t acc[8][2];
#pragma unroll
    for (int i = 0; i < 8; i++) { acc[i][0] = 0ull; acc[i][1] = 0ull; }

    for (int k0 = 0; k0 < FIN; k0 += 32) {
#pragma unroll
        for (int e = 0; e < 8; e++) {
            int idx = t + e * 256;
            int r = idx >> 5, c = idx & 31;
            xs[r * 33 + c] = x[(size_t)(row0 + r) * FIN + k0 + c];
        }
#pragma unroll
        for (int e = 0; e < 4; e++) {
            int vidx = t + e * 256;
            int kk = vidx >> 5, cv = vidx & 31;
            ((float4*)ws)[kk * 32 + cv] =
                ((const float4*)W)[(size_t)(k0 + kk) * 32 + cv];
        }
        __syncthreads();
#pragma unroll
        for (int kk = 0; kk < 32; kk++) {
            ulonglong2 wv = ((const ulonglong2*)ws)[kk * 32 + tx];
#pragma unroll
            for (int i = 0; i < 8; i++) {
                float xv = xs[(ty * 8 + i) * 33 + kk];
                uint64_t xp;
                asm("mov.b64 %0, {%1, %1};" : "=l"(xp) : "f"(xv));
                FFMA2(acc[i][0], xp, wv.x);
                FFMA2(acc[i][1], xp, wv.y);
            }
        }
        __syncthreads();
    }

    const float4 avs = ((const float4*)a)[tx];
    const float4 avd = ((const float4*)a)[32 + tx];
#pragma unroll
    for (int i = 0; i < 8; i++) {
        int row = row0 + ty * 8 + i;
        float4 v;
        asm("mov.b64 {%0, %1}, %2;" : "=f"(v.x), "=f"(v.y) : "l"(acc[i][0]));
        asm("mov.b64 {%0, %1}, %2;" : "=f"(v.z), "=f"(v.w) : "l"(acc[i][1]));
        ((float4*)g_h)[(size_t)row * 32 + tx] = v;
        float ps = v.x * avs.x + v.y * avs.y + v.z * avs.z + v.w * avs.w;
        float pd = v.x * avd.x + v.y * avd.y + v.z * avd.z + v.w * avd.w;
#pragma unroll
        for (int o = 16; o > 0; o >>= 1) {
            ps += __shfl_xor_sync(0xffffffffu, ps, o);
            pd += __shfl_xor_sync(0xffffffffu, pd, o);
        }
        if (tx == 0) { g_fs[row] = ps; g_fd[row] = pd; }
    }
}

// ---------------------------------------------------------------------------
// Kernel 1b: per-batch max of f_dst (for the safe softmax upper bound).
// ---------------------------------------------------------------------------
__global__ void fdmax_kernel() {
    __shared__ float red[8];
    const int b = blockIdx.x;
    const int t = threadIdx.x;
    float m = -INFINITY;
    for (int j = t; j < NN; j += 256) m = fmaxf(m, g_fd[b * NN + j]);
#pragma unroll
    for (int o = 16; o > 0; o >>= 1)
        m = fmaxf(m, __shfl_xor_sync(0xffffffffu, m, o));
    if ((t & 31) == 0) red[t >> 5] = m;
    __syncthreads();
    if (t == 0) {
        float mm = red[0];
#pragma unroll
        for (int w = 1; w < 8; w++) mm = fmaxf(mm, red[w]);
        g_fdmax[b] = mm;
    }
}

// ---------------------------------------------------------------------------
// Kernel 2: fused gated attention, non-online softmax (safe precomputed max),
// f32x2 accumulate. Block: 64 queries, 256 threads; thread = (trow=t/16,
// tcol=t%16): rows trow*4+{0..3}, cols tcol*4+{0..3} and 64+tcol*4+{0..3}.
// ---------------------------------------------------------------------------
extern __shared__ char s_dyn[];

__global__ __launch_bounds__(256, 2)
void attn_kernel(const float* __restrict__ coord, float* __restrict__ out) {
    float*    hk  = (float*)s_dyn;                       // KT*FOUT floats (32KB)
    uint64_t* ps2 = (uint64_t*)(s_dyn + KT * FOUT * 4);  // QT*PS2 u64 (33792B)
    float*    ck  = (float*)((char*)ps2 + QT * PS2 * 8); // KT*4 floats
    float*    fdk = ck + KT * 4;                         // KT floats

    const int t    = threadIdx.x;
    const int tcol = t & 15;
    const int trow = t >> 4;
    const int b    = blockIdx.x >> 5;
    const int q0   = (blockIdx.x & 31) * QT;

    const float fdmax = g_fdmax[b];

    float fs[4], M[4], cix[4], ciy[4], ciz[4], lsum[4];
#pragma unroll
    for (int i = 0; i < 4; i++) {
        int q = q0 + trow * 4 + i;
        fs[i] = g_fs[b * NN + q];
        M[i]  = fmaxf(0.f, fs[i] + fdmax);   // safe upper bound on row max
        const float* cp = coord + ((size_t)b * NN + q) * 3;
        cix[i] = cp[0]; ciy[i] = cp[1]; ciz[i] = cp[2];
        lsum[i] = 0.f;
    }
    uint64_t acc[4][4];
#pragma unroll
    for (int i = 0; i < 4; i++)
#pragma unroll
        for (int c = 0; c < 4; c++) acc[i][c] = 0ull;

    for (int k0 = 0; k0 < NN; k0 += KT) {
        __syncthreads();
        const float4* hsrc = (const float4*)(g_h + ((size_t)b * NN + k0) * FOUT);
#pragma unroll
        for (int e = 0; e < 8; e++)
            ((float4*)hk)[t + e * 256] = hsrc[t + e * 256];
        if (t < KT) {
            const float* cp = coord + ((size_t)b * NN + k0 + t) * 3;
            ck[t * 4 + 0] = cp[0];
            ck[t * 4 + 1] = cp[1];
            ck[t * 4 + 2] = cp[2];
            fdk[t] = g_fd[b * NN + k0 + t];
        }
        __syncthreads();

        // ---- logits -> p = exp(v - M), stored to smem pre-duplicated ----
        float p[4][4];
#pragma unroll
        for (int jj = 0; jj < 4; jj++) {
            int j = tcol * 4 + jj;
            float cjx = ck[j * 4], cjy = ck[j * 4 + 1], cjz = ck[j * 4 + 2];
            float fd = fdk[j];
#pragma unroll
            for (int i = 0; i < 4; i++) {
                float dx = cix[i] - cjx, dy = ciy[i] - cjy, dz = ciz[i] - cjz;
                float d2 = dx * dx + dy * dy + dz * dz;
                float loc = __expf(-CUTOFF * d2);
                float e = fs[i] + fd;
                e = e > 0.f ? e : ALPHA * e;
                float v = (loc > 0.01f) ? e * loc : NEGINF;
                float pv = __expf(v - M[i]);
                p[i][jj] = pv;
                lsum[i] += pv;
            }
        }
#pragma unroll
        for (int i = 0; i < 4; i++) {
            int row = trow * 4 + i;
            float4 d0 = make_float4(p[i][0], p[i][0], p[i][1], p[i][1]);
            float4 d1 = make_float4(p[i][2], p[i][2], p[i][3], p[i][3]);
            float4* dst = (float4*)(ps2 + row * PS2 + tcol * 4);
            dst[0] = d0;
            dst[1] = d1;
        }
        __syncwarp();   // p rows are produced & consumed within the same 16-lane group

        // ---- accumulate: acc += p * hk (pure LDS + FFMA2) ----
#pragma unroll 2
        for (int j0 = 0; j0 < KT; j0 += 4) {
            uint64_t pr[4][4];
#pragma unroll
            for (int i = 0; i < 4; i++) {
                const ulonglong2* pp =
                    (const ulonglong2*)(ps2 + (trow * 4 + i) * PS2 + j0);
                ulonglong2 pa = pp[0], pb = pp[1];
                pr[i][0] = pa.x; pr[i][1] = pa.y;
                pr[i][2] = pb.x; pr[i][3] = pb.y;
            }
#pragma unroll
            for (int jj = 0; jj < 4; jj++) {
                ulonglong2 h0 =
                    *(const ulonglong2*)(hk + (j0 + jj) * FOUT + tcol * 4);
                ulonglong2 h1 =
                    *(const ulonglong2*)(hk + (j0 + jj) * FOUT + 64 + tcol * 4);
#pragma unroll
                for (int i = 0; i < 4; i++) {
                    FFMA2(acc[i][0], pr[i][jj], h0.x);
                    FFMA2(acc[i][1], pr[i][jj], h0.y);
                    FFMA2(acc[i][2], pr[i][jj], h1.x);
                    FFMA2(acc[i][3], pr[i][jj], h1.y);
                }
            }
        }
    }

    // ---- epilogue: reduce l across the 16 lanes, normalize, ELU, store ----
#pragma unroll
    for (int o = 1; o < 16; o <<= 1)
#pragma unroll
        for (int i = 0; i < 4; i++)
            lsum[i] += __shfl_xor_sync(0xffffffffu, lsum[i], o);

#pragma unroll
    for (int i = 0; i < 4; i++) {
        int q = q0 + trow * 4 + i;
        float inv = 1.f / lsum[i];
        float o8[8];
        asm("mov.b64 {%0, %1}, %2;" : "=f"(o8[0]), "=f"(o8[1]) : "l"(acc[i][0]));
        asm("mov.b64 {%0, %1}, %2;" : "=f"(o8[2]), "=f"(o8[3]) : "l"(acc[i][1]));
        asm("mov.b64 {%0, %1}, %2;" : "=f"(o8[4]), "=f"(o8[5]) : "l"(acc[i][2]));
        asm("mov.b64 {%0, %1}, %2;" : "=f"(o8[6]), "=f"(o8[7]) : "l"(acc[i][3]));
#pragma unroll
        for (int c = 0; c < 8; c++) {
            float v = o8[c] * inv;
            o8[c] = v > 0.f ? v : (__expf(v) - 1.f);
        }
        float4* op = (float4*)(out + ((size_t)b * NN + q) * FOUT);
        op[tcol]      = make_float4(o8[0], o8[1], o8[2], o8[3]);
        op[16 + tcol] = make_float4(o8[4], o8[5], o8[6], o8[7]);
    }
}

// ---------------------------------------------------------------------------
extern "C" void kernel_launch(void* const* d_in, const int* in_sizes, int n_in,
                              void* d_out, int out_size) {
    const float *x = nullptr, *coord = nullptr, *W = nullptr, *a = nullptr;
    for (int i = 0; i < n_in; i++) {
        switch (in_sizes[i]) {
            case BB * NN * FIN: x     = (const float*)d_in[i]; break;
            case BB * NN * 3:   coord = (const float*)d_in[i]; break;
            case FIN * FOUT:    W     = (const float*)d_in[i]; break;
            case 2 * FOUT:      a     = (const float*)d_in[i]; break;
            default: break;
        }
    }
    float* out = (float*)d_out;

    gemm_h_kernel<<<(BB * NN) / 64, 256>>>(x, W, a);
    fdmax_kernel<<<BB, 256>>>();

    const int smem = KT * FOUT * 4 + QT * PS2 * 8 + KT * 4 * 4 + KT * 4;
    static bool attr_set = false;
    if (!attr_set) {
        cudaFuncSetAttribute(attn_kernel,
                             cudaFuncAttributeMaxDynamicSharedMemorySize, smem);
        attr_set = true;
    }
    attn_kernel<<<BB * (NN / QT), 256, smem>>>(coord, out);
}

// round 6
// speedup vs baseline: 1.5829x; 1.5829x over previous
#include <cuda_runtime.h>
#include <math.h>
#include <stdint.h>

#define BB 8
#define NN 2048
#define FIN 256
#define FOUT 128
#define ALPHA 0.2f
#define CUTOFF 0.1f
#define NEGINF -9e15f

#define MT 128          // queries per CTA
#define KT 64           // keys per tile
#define HS 136          // H smem row stride (floats): conflict-free B-frag loads

// Scratch (no cudaMalloc allowed)
__device__ float g_h_hi[BB * NN * FOUT];
__device__ float g_h_lo[BB * NN * FOUT];
__device__ float g_fs[BB * NN];
__device__ float g_fd[BB * NN];
__device__ float g_fdmax[BB];

// ---------------------------------------------------------------------------
// helpers
// ---------------------------------------------------------------------------
__device__ __forceinline__ uint32_t smem_u32(const void* p) {
    uint32_t a;
    asm("{ .reg .u64 t; cvta.to.shared.u64 t, %1; cvt.u32.u64 %0, t; }"
        : "=r"(a) : "l"(p));
    return a;
}
__device__ __forceinline__ void tf32split(float v, uint32_t& hi, uint32_t& lo) {
    asm("cvt.rna.tf32.f32 %0, %1;" : "=r"(hi) : "f"(v));
    float l = v - __uint_as_float(hi);
    asm("cvt.rna.tf32.f32 %0, %1;" : "=r"(lo) : "f"(l));
}
__device__ __forceinline__ uint32_t tf32r(float v) {
    uint32_t r;
    asm("cvt.rna.tf32.f32 %0, %1;" : "=r"(r) : "f"(v));
    return r;
}
#define MMA_TF32(d, a, b0, b1)                                                  \
    asm volatile("mma.sync.aligned.m16n8k8.row.col.f32.tf32.tf32.f32 "          \
                 "{%0,%1,%2,%3},{%4,%5,%6,%7},{%8,%9},{%0,%1,%2,%3};"           \
                 : "+f"((d)[0]), "+f"((d)[1]), "+f"((d)[2]), "+f"((d)[3])       \
                 : "r"((a)[0]), "r"((a)[1]), "r"((a)[2]), "r"((a)[3]),          \
                   "r"(b0), "r"(b1))
#define CP16(dst, src) \
    asm volatile("cp.async.cg.shared.global [%0], [%1], 16;" :: "r"(dst), "l"(src))
#define CP4(dst, src) \
    asm volatile("cp.async.ca.shared.global [%0], [%1], 4;" :: "r"(dst), "l"(src))
#define CP_COMMIT() asm volatile("cp.async.commit_group;" ::: "memory")
#define CP_WAIT(n)  asm volatile("cp.async.wait_group %0;" :: "n"(n) : "memory")

// ---------------------------------------------------------------------------
// Kernel 1: h = x @ W (FFMA), epilogue splits h into tf32 hi/lo and computes
// f_src = h@a[:128], f_dst = h@a[128:].
// ---------------------------------------------------------------------------
__global__ __launch_bounds__(256, 2)
void gemm_h_kernel(const float* __restrict__ x, const float* __restrict__ W,
                   const float* __restrict__ a) {
    __shared__ float xs[64 * 33];
    __shared__ float ws[32 * 128];

    const int t  = threadIdx.x;
    const int tx = t & 31;
    const int ty = t >> 5;
    const int row0 = blockIdx.x * 64;

    float acc[8][4];
#pragma unroll
    for (int i = 0; i < 8; i++)
#pragma unroll
        for (int j = 0; j < 4; j++) acc[i][j] = 0.f;

    for (int k0 = 0; k0 < FIN; k0 += 32) {
#pragma unroll
        for (int e = 0; e < 8; e++) {
            int idx = t + e * 256;
            int r = idx >> 5, c = idx & 31;
            xs[r * 33 + c] = x[(size_t)(row0 + r) * FIN + k0 + c];
        }
#pragma unroll
        for (int e = 0; e < 4; e++) {
            int vidx = t + e * 256;
            int kk = vidx >> 5, cv = vidx & 31;
            ((float4*)ws)[kk * 32 + cv] =
                ((const float4*)W)[(size_t)(k0 + kk) * 32 + cv];
        }
        __syncthreads();
#pragma unroll
        for (int kk = 0; kk < 32; kk++) {
            float4 wv = ((float4*)ws)[kk * 32 + tx];
#pragma unroll
            for (int i = 0; i < 8; i++) {
                float xv = xs[(ty * 8 + i) * 33 + kk];
                acc[i][0] += xv * wv.x;
                acc[i][1] += xv * wv.y;
                acc[i][2] += xv * wv.z;
                acc[i][3] += xv * wv.w;
            }
        }
        __syncthreads();
    }

    const float4 avs = ((const float4*)a)[tx];
    const float4 avd = ((const float4*)a)[32 + tx];
#pragma unroll
    for (int i = 0; i < 8; i++) {
        int row = row0 + ty * 8 + i;
        float4 v = make_float4(acc[i][0], acc[i][1], acc[i][2], acc[i][3]);
        // tf32 hi/lo split
        float4 hv, lv;
        uint32_t hb, lb;
        tf32split(v.x, hb, lb); hv.x = __uint_as_float(hb); lv.x = __uint_as_float(lb);
        tf32split(v.y, hb, lb); hv.y = __uint_as_float(hb); lv.y = __uint_as_float(lb);
        tf32split(v.z, hb, lb); hv.z = __uint_as_float(hb); lv.z = __uint_as_float(lb);
        tf32split(v.w, hb, lb); hv.w = __uint_as_float(hb); lv.w = __uint_as_float(lb);
        ((float4*)g_h_hi)[(size_t)row * 32 + tx] = hv;
        ((float4*)g_h_lo)[(size_t)row * 32 + tx] = lv;

        float ps = v.x * avs.x + v.y * avs.y + v.z * avs.z + v.w * avs.w;
        float pd = v.x * avd.x + v.y * avd.y + v.z * avd.z + v.w * avd.w;
#pragma unroll
        for (int o = 16; o > 0; o >>= 1) {
            ps += __shfl_xor_sync(0xffffffffu, ps, o);
            pd += __shfl_xor_sync(0xffffffffu, pd, o);
        }
        if (tx == 0) { g_fs[row] = ps; g_fd[row] = pd; }
    }
}

// ---------------------------------------------------------------------------
// Kernel 1b: per-batch max of f_dst
// ---------------------------------------------------------------------------
__global__ void fdmax_kernel() {
    __shared__ float red[8];
    const int b = blockIdx.x;
    const int t = threadIdx.x;
    float m = -INFINITY;
    for (int j = t; j < NN; j += 256) m = fmaxf(m, g_fd[b * NN + j]);
#pragma unroll
    for (int o = 16; o > 0; o >>= 1)
        m = fmaxf(m, __shfl_xor_sync(0xffffffffu, m, o));
    if ((t & 31) == 0) red[t >> 5] = m;
    __syncthreads();
    if (t == 0) {
        float mm = red[0];
#pragma unroll
        for (int w = 1; w < 8; w++) mm = fmaxf(mm, red[w]);
        g_fdmax[b] = mm;
    }
}

// ---------------------------------------------------------------------------
// Kernel 2: fused gated attention with mma.sync tf32 split-split P@H.
// 128 queries/CTA, 8 warps; warp w owns q rows [w*16, w*16+16).
// A-fragment p computed in-lane (no smem); H hi/lo tiles double-buffered
// via cp.async; accumulators persistent in registers (16 n-tiles x 4).
//
// smem per buffer: Hhi[64][136] (34816B), Hlo (34816B), ck[64][4] (1024B),
// fd[64] (256B)  => 70912B; two buffers => 141824B.
// ---------------------------------------------------------------------------
#define BUFSZ   70912
#define OFF_HHI 0
#define OFF_HLO 34816
#define OFF_CK  69632
#define OFF_FD  70656
#define SM_TOTAL (2 * BUFSZ)

extern __shared__ char s_raw[];

__device__ __forceinline__ void prefetch_tile(uint32_t sbase, int buf, int b,
                                              int k0, int t,
                                              const float* __restrict__ coord) {
    const uint32_t bb = sbase + buf * BUFSZ;
    const float4* hsrc_hi = (const float4*)(g_h_hi + ((size_t)b * NN + k0) * FOUT);
    const float4* hsrc_lo = (const float4*)(g_h_lo + ((size_t)b * NN + k0) * FOUT);
#pragma unroll
    for (int e = 0; e < 8; e++) {
        int idx = t + e * 256;          // 0..2047
        int r = idx >> 5, c4 = idx & 31;
        uint32_t doff = (uint32_t)(r * HS + c4 * 4) * 4u;
        CP16(bb + OFF_HHI + doff, (const void*)(hsrc_hi + idx));
        CP16(bb + OFF_HLO + doff, (const void*)(hsrc_lo + idx));
    }
    if (t < 192) {
        int k = t / 3, c = t - k * 3;
        CP4(bb + OFF_CK + (uint32_t)(k * 4 + c) * 4u,
            (const void*)(coord + ((size_t)b * NN + k0 + k) * 3 + c));
    }
    if (t < KT) {
        CP4(bb + OFF_FD + (uint32_t)t * 4u,
            (const void*)(g_fd + (size_t)b * NN + k0 + t));
    }
}

__device__ __forceinline__ float pcalc(float fs, float M, float cx, float cy,
                                       float cz, float kx, float ky, float kz,
                                       float fd) {
    float dx = cx - kx, dy = cy - ky, dz = cz - kz;
    float d2 = dx * dx + dy * dy + dz * dz;
    float loc = __expf(-CUTOFF * d2);
    float e = fs + fd;
    e = fmaxf(e, ALPHA * e);
    float v = (loc > 0.01f) ? e * loc : NEGINF;
    return __expf(v - M);
}

__global__ __launch_bounds__(256, 1)
void attn_kernel(const float* __restrict__ coord, float* __restrict__ out) {
    const uint32_t sbase = smem_u32(s_raw);
    const int t   = threadIdx.x;
    const int lid = t & 31;
    const int wid = t >> 5;
    const int g   = lid >> 2;        // 0..7
    const int t4  = lid & 3;         // 0..3
    const int b   = blockIdx.x >> 4;
    const int q0  = (blockIdx.x & 15) * MT;
    const int row0 = q0 + wid * 16 + g;      // query row for a0/a2, c0/c1
    const int row1 = row0 + 8;               // query row for a1/a3, c2/c3

    const float fdmax = g_fdmax[b];
    const float fs0 = g_fs[b * NN + row0];
    const float fs1 = g_fs[b * NN + row1];
    const float M0 = fmaxf(0.f, fs0 + fdmax);
    const float M1 = fmaxf(0.f, fs1 + fdmax);
    const float* cp0 = coord + ((size_t)b * NN + row0) * 3;
    const float* cp1 = coord + ((size_t)b * NN + row1) * 3;
    const float c0x = cp0[0], c0y = cp0[1], c0z = cp0[2];
    const float c1x = cp1[0], c1y = cp1[1], c1z = cp1[2];

    float acc[16][4];
#pragma unroll
    for (int nt = 0; nt < 16; nt++)
#pragma unroll
        for (int c = 0; c < 4; c++) acc[nt][c] = 0.f;
    float lsum0 = 0.f, lsum1 = 0.f;

    prefetch_tile(sbase, 0, b, 0, t, coord);
    CP_COMMIT();

    for (int kt = 0; kt < NN / KT; kt++) {
        const int buf = kt & 1;
        __syncthreads();               // everyone done with buffer (kt+1)&1
        if (kt + 1 < NN / KT) {
            prefetch_tile(sbase, buf ^ 1, b, (kt + 1) * KT, t, coord);
            CP_COMMIT();
            CP_WAIT(1);                // tile kt's group complete
        } else {
            CP_WAIT(0);
        }
        __syncthreads();

        const float* ckb = (const float*)(s_raw + buf * BUFSZ + OFF_CK);
        const float* fdb = (const float*)(s_raw + buf * BUFSZ + OFF_FD);
        const float* Hhi = (const float*)(s_raw + buf * BUFSZ + OFF_HHI);
        const float* Hlo = (const float*)(s_raw + buf * BUFSZ + OFF_HLO);

        // ---- A fragments: p computed directly in fragment lanes ----
        uint32_t ahi[8][4], alo[8][4];
#pragma unroll
        for (int kc = 0; kc < 8; kc++) {
            int k1 = kc * 8 + t4;
            int k2 = k1 + 4;
            float k1x = ckb[k1 * 4], k1y = ckb[k1 * 4 + 1], k1z = ckb[k1 * 4 + 2];
            float k2x = ckb[k2 * 4], k2y = ckb[k2 * 4 + 1], k2z = ckb[k2 * 4 + 2];
            float fd1 = fdb[k1], fd2 = fdb[k2];
            float p00 = pcalc(fs0, M0, c0x, c0y, c0z, k1x, k1y, k1z, fd1);
            float p10 = pcalc(fs1, M1, c1x, c1y, c1z, k1x, k1y, k1z, fd1);
            float p01 = pcalc(fs0, M0, c0x, c0y, c0z, k2x, k2y, k2z, fd2);
            float p11 = pcalc(fs1, M1, c1x, c1y, c1z, k2x, k2y, k2z, fd2);
            lsum0 += p00 + p01;
            lsum1 += p10 + p11;
            tf32split(p00, ahi[kc][0], alo[kc][0]);
            tf32split(p10, ahi[kc][1], alo[kc][1]);
            tf32split(p01, ahi[kc][2], alo[kc][2]);
            tf32split(p11, ahi[kc][3], alo[kc][3]);
        }

        // ---- MMA sweep: 16 n-tiles x 8 k-chunks x 3 products ----
#pragma unroll
        for (int nt = 0; nt < 16; nt++) {
#pragma unroll
            for (int kc = 0; kc < 8; kc++) {
                int ridx = (kc * 8 + t4) * HS + nt * 8 + g;
                uint32_t bh0 = __float_as_uint(Hhi[ridx]);
                uint32_t bh1 = __float_as_uint(Hhi[ridx + 4 * HS]);
                uint32_t bl0 = __float_as_uint(Hlo[ridx]);
                uint32_t bl1 = __float_as_uint(Hlo[ridx + 4 * HS]);
                MMA_TF32(acc[nt], ahi[kc], bh0, bh1);
                MMA_TF32(acc[nt], ahi[kc], bl0, bl1);
                MMA_TF32(acc[nt], alo[kc], bh0, bh1);
            }
        }
    }

    // ---- row sums: quad all-reduce (lanes sharing g) ----
    lsum0 += __shfl_xor_sync(0xffffffffu, lsum0, 1);
    lsum0 += __shfl_xor_sync(0xffffffffu, lsum0, 2);
    lsum1 += __shfl_xor_sync(0xffffffffu, lsum1, 1);
    lsum1 += __shfl_xor_sync(0xffffffffu, lsum1, 2);
    const float inv0 = 1.f / lsum0;
    const float inv1 = 1.f / lsum1;

    // ---- epilogue: normalize, ELU, store ----
    float* o0 = out + ((size_t)b * NN + row0) * FOUT;
    float* o1 = out + ((size_t)b * NN + row1) * FOUT;
#pragma unroll
    for (int nt = 0; nt < 16; nt++) {
        float v0 = acc[nt][0] * inv0, v1 = acc[nt][1] * inv0;
        float v2 = acc[nt][2] * inv1, v3 = acc[nt][3] * inv1;
        v0 = v0 > 0.f ? v0 : (__expf(v0) - 1.f);
        v1 = v1 > 0.f ? v1 : (__expf(v1) - 1.f);
        v2 = v2 > 0.f ? v2 : (__expf(v2) - 1.f);
        v3 = v3 > 0.f ? v3 : (__expf(v3) - 1.f);
        int col = nt * 8 + 2 * t4;
        *(float2*)(o0 + col) = make_float2(v0, v1);
        *(float2*)(o1 + col) = make_float2(v2, v3);
    }
}

// ---------------------------------------------------------------------------
extern "C" void kernel_launch(void* const* d_in, const int* in_sizes, int n_in,
                              void* d_out, int out_size) {
    const float *x = nullptr, *coord = nullptr, *W = nullptr, *a = nullptr;
    for (int i = 0; i < n_in; i++) {
        switch (in_sizes[i]) {
            case BB * NN * FIN: x     = (const float*)d_in[i]; break;
            case BB * NN * 3:   coord = (const float*)d_in[i]; break;
            case FIN * FOUT:    W     = (const float*)d_in[i]; break;
            case 2 * FOUT:      a     = (const float*)d_in[i]; break;
            default: break;
        }
    }
    float* out = (float*)d_out;

    gemm_h_kernel<<<(BB * NN) / 64, 256>>>(x, W, a);
    fdmax_kernel<<<BB, 256>>>();

    static bool attr_set = false;
    if (!attr_set) {
        cudaFuncSetAttribute(attn_kernel,
                             cudaFuncAttributeMaxDynamicSharedMemorySize, SM_TOTAL);
        attr_set = true;
    }
    attn_kernel<<<BB * (NN / MT), 256, SM_TOTAL>>>(coord, out);
}

// round 11
// speedup vs baseline: 2.1959x; 1.3872x over previous
#include <cuda_runtime.h>
#include <math.h>
#include <stdint.h>

#define BB 8
#define NN 2048
#define FIN 256
#define FOUT 128
#define ALPHA 0.2f
#define CUTOFF 0.1f
#define NEGINF -9e15f

#define MT 128          // queries per CTA
#define KT 64           // keys per tile
#define HROW 272        // H smem row stride bytes (136 bf16): LDSM conflict-free

// Scratch (no cudaMalloc allowed)
__device__ uint16_t g_hb_hi[BB * NN * FOUT];   // bf16 hi
__device__ uint16_t g_hb_lo[BB * NN * FOUT];   // bf16 residual
__device__ float g_fs[BB * NN];
__device__ float g_fd[BB * NN];
__device__ float g_fdmax[BB];

// ---------------------------------------------------------------------------
// helpers
// ---------------------------------------------------------------------------
__device__ __forceinline__ uint32_t smem_u32(const void* p) {
    uint32_t a;
    asm("{ .reg .u64 t; cvta.to.shared.u64 t, %1; cvt.u32.u64 %0, t; }"
        : "=r"(a) : "l"(p));
    return a;
}
// pack two f32 -> bf16x2 (lo half = pe, hi half = po)
__device__ __forceinline__ uint32_t bfpack(float po, float pe) {
    uint32_t r;
    asm("cvt.rn.bf16x2.f32 %0, %1, %2;" : "=r"(r) : "f"(po), "f"(pe));
    return r;
}
#define MMA_BF16(d, a, b0, b1)                                                  \
    asm volatile("mma.sync.aligned.m16n8k16.row.col.f32.bf16.bf16.f32 "         \
                 "{%0,%1,%2,%3},{%4,%5,%6,%7},{%8,%9},{%0,%1,%2,%3};"           \
                 : "+f"((d)[0]), "+f"((d)[1]), "+f"((d)[2]), "+f"((d)[3])       \
                 : "r"((a)[0]), "r"((a)[1]), "r"((a)[2]), "r"((a)[3]),          \
                   "r"(b0), "r"(b1))
#define LDSM4T(r0, r1, r2, r3, addr)                                            \
    asm volatile("ldmatrix.sync.aligned.m8n8.x4.trans.shared.b16 "              \
                 "{%0,%1,%2,%3}, [%4];"                                         \
                 : "=r"(r0), "=r"(r1), "=r"(r2), "=r"(r3) : "r"(addr))
#define CP16(dst, src) \
    asm volatile("cp.async.cg.shared.global [%0], [%1], 16;" :: "r"(dst), "l"(src))
#define CP4(dst, src) \
    asm volatile("cp.async.ca.shared.global [%0], [%1], 4;" :: "r"(dst), "l"(src))
#define CP_COMMIT() asm volatile("cp.async.commit_group;" ::: "memory")
#define CP_WAIT(n)  asm volatile("cp.async.wait_group %0;" :: "n"(n) : "memory")

// ---------------------------------------------------------------------------
// Kernel 1: h = x @ W (FFMA); epilogue: bf16 hi/lo split of h + f_src/f_dst.
// ---------------------------------------------------------------------------
__global__ __launch_bounds__(256, 2)
void gemm_h_kernel(const float* __restrict__ x, const float* __restrict__ W,
                   const float* __restrict__ a) {
    __shared__ float xs[64 * 33];
    __shared__ float ws[32 * 128];

    const int t  = threadIdx.x;
    const int tx = t & 31;
    const int ty = t >> 5;
    const int row0 = blockIdx.x * 64;

    float acc[8][4];
#pragma unroll
    for (int i = 0; i < 8; i++)
#pragma unroll
        for (int j = 0; j < 4; j++) acc[i][j] = 0.f;

    for (int k0 = 0; k0 < FIN; k0 += 32) {
#pragma unroll
        for (int e = 0; e < 8; e++) {
            int idx = t + e * 256;
            int r = idx >> 5, c = idx & 31;
            xs[r * 33 + c] = x[(size_t)(row0 + r) * FIN + k0 + c];
        }
#pragma unroll
        for (int e = 0; e < 4; e++) {
            int vidx = t + e * 256;
            int kk = vidx >> 5, cv = vidx & 31;
            ((float4*)ws)[kk * 32 + cv] =
                ((const float4*)W)[(size_t)(k0 + kk) * 32 + cv];
        }
        __syncthreads();
#pragma unroll
        for (int kk = 0; kk < 32; kk++) {
            float4 wv = ((float4*)ws)[kk * 32 + tx];
#pragma unroll
            for (int i = 0; i < 8; i++) {
                float xv = xs[(ty * 8 + i) * 33 + kk];
                acc[i][0] += xv * wv.x;
                acc[i][1] += xv * wv.y;
                acc[i][2] += xv * wv.z;
                acc[i][3] += xv * wv.w;
            }
        }
        __syncthreads();
    }

    const float4 avs = ((const float4*)a)[tx];
    const float4 avd = ((const float4*)a)[32 + tx];
#pragma unroll
    for (int i = 0; i < 8; i++) {
        int row = row0 + ty * 8 + i;
        float4 v = make_float4(acc[i][0], acc[i][1], acc[i][2], acc[i][3]);
        // bf16 hi
        uint32_t d0 = bfpack(v.y, v.x);
        uint32_t d1 = bfpack(v.w, v.z);
        // residuals
        float r0 = v.x - __uint_as_float(d0 << 16);
        float r1 = v.y - __uint_as_float(d0 & 0xffff0000u);
        float r2 = v.z - __uint_as_float(d1 << 16);
        float r3 = v.w - __uint_as_float(d1 & 0xffff0000u);
        uint32_t e0 = bfpack(r1, r0);
        uint32_t e1 = bfpack(r3, r2);
        ((uint2*)(g_hb_hi + (size_t)row * FOUT))[tx] = make_uint2(d0, d1);
        ((uint2*)(g_hb_lo + (size_t)row * FOUT))[tx] = make_uint2(e0, e1);

        float ps = v.x * avs.x + v.y * avs.y + v.z * avs.z + v.w * avs.w;
        float pd = v.x * avd.x + v.y * avd.y + v.z * avd.z + v.w * avd.w;
#pragma unroll
        for (int o = 16; o > 0; o >>= 1) {
            ps += __shfl_xor_sync(0xffffffffu, ps, o);
            pd += __shfl_xor_sync(0xffffffffu, pd, o);
        }
        if (tx == 0) { g_fs[row] = ps; g_fd[row] = pd; }
    }
}

// ---------------------------------------------------------------------------
// Kernel 1b: per-batch max of f_dst
// ---------------------------------------------------------------------------
__global__ void fdmax_kernel() {
    __shared__ float red[8];
    const int b = blockIdx.x;
    const int t = threadIdx.x;
    float m = -INFINITY;
    for (int j = t; j < NN; j += 256) m = fmaxf(m, g_fd[b * NN + j]);
#pragma unroll
    for (int o = 16; o > 0; o >>= 1)
        m = fmaxf(m, __shfl_xor_sync(0xffffffffu, m, o));
    if ((t & 31) == 0) red[t >> 5] = m;
    __syncthreads();
    if (t == 0) {
        float mm = red[0];
#pragma unroll
        for (int w = 1; w < 8; w++) mm = fmaxf(mm, red[w]);
        g_fdmax[b] = mm;
    }
}

// ---------------------------------------------------------------------------
// Kernel 2: fused gated attention, bf16 m16n8k16 split-split (3 products),
// ldmatrix.x4.trans B-frags, A-frags computed in-lane.
// smem buffer: Hhi[64][136bf16] 17408B, Hlo 17408B, ck 1024B, fd 256B.
// ---------------------------------------------------------------------------
#define OFF_HHI 0
#define OFF_HLO 17408
#define OFF_CK  34816
#define OFF_FD  35840
#define BUFSZ   36096
#define SM_TOTAL (2 * BUFSZ)

extern __shared__ char s_raw[];

__device__ __forceinline__ void prefetch_tile(uint32_t sbase, int buf, int b,
                                              int k0, int t,
                                              const float* __restrict__ coord) {
    const uint32_t bb = sbase + buf * BUFSZ;
    const char* hs = (const char*)(g_hb_hi + ((size_t)b * NN + k0) * FOUT);
    const char* ls = (const char*)(g_hb_lo + ((size_t)b * NN + k0) * FOUT);
#pragma unroll
    for (int e = 0; e < 4; e++) {
        int idx = t + e * 256;          // 0..1023
        int r = idx >> 4, c = idx & 15; // row, 16B chunk
        uint32_t doff = (uint32_t)(r * HROW + c * 16);
        uint32_t soff = (uint32_t)(r * 256 + c * 16);
        CP16(bb + OFF_HHI + doff, (const void*)(hs + soff));
        CP16(bb + OFF_HLO + doff, (const void*)(ls + soff));
    }
    if (t < 192) {
        int k = t / 3, c = t - k * 3;
        CP4(bb + OFF_CK + (uint32_t)(k * 4 + c) * 4u,
            (const void*)(coord + ((size_t)b * NN + k0 + k) * 3 + c));
    }
    if (t < KT) {
        CP4(bb + OFF_FD + (uint32_t)t * 4u,
            (const void*)(g_fd + (size_t)b * NN + k0 + t));
    }
}

__device__ __forceinline__ float pcalc(float fs, float M, float cx, float cy,
                                       float cz, float kx, float ky, float kz,
                                       float fd) {
    float dx = cx - kx, dy = cy - ky, dz = cz - kz;
    float d2 = dx * dx + dy * dy + dz * dz;
    float loc = __expf(-CUTOFF * d2);
    float e = fs + fd;
    e = fmaxf(e, ALPHA * e);
    float v = (loc > 0.01f) ? e * loc : NEGINF;
    return __expf(v - M);
}

__global__ __launch_bounds__(256, 1)
void attn_kernel(const float* __restrict__ coord, float* __restrict__ out) {
    const uint32_t sbase = smem_u32(s_raw);
    const int t   = threadIdx.x;
    const int lid = t & 31;
    const int wid = t >> 5;
    const int g   = lid >> 2;        // 0..7
    const int t4  = lid & 3;         // 0..3
    const int b   = blockIdx.x >> 4;
    const int q0  = (blockIdx.x & 15) * MT;
    const int row0 = q0 + wid * 16 + g;
    const int row1 = row0 + 8;

    const float fdmax = g_fdmax[b];
    const float fs0 = g_fs[b * NN + row0];
    const float fs1 = g_fs[b * NN + row1];
    const float M0 = fmaxf(0.f, fs0 + fdmax);
    const float M1 = fmaxf(0.f, fs1 + fdmax);
    const float* cp0 = coord + ((size_t)b * NN + row0) * 3;
    const float* cp1 = coord + ((size_t)b * NN + row1) * 3;
    const float c0x = cp0[0], c0y = cp0[1], c0z = cp0[2];
    const float c1x = cp1[0], c1y = cp1[1], c1z = cp1[2];

    // ldmatrix lane offset: key = (lid&15), feat-half = (lid>>4)*8
    const uint32_t loff = (uint32_t)((lid & 15) * HROW + (lid >> 4) * 16);

    float acc[16][4];
#pragma unroll
    for (int nt = 0; nt < 16; nt++)
#pragma unroll
        for (int c = 0; c < 4; c++) acc[nt][c] = 0.f;
    float lsum0 = 0.f, lsum1 = 0.f;

    prefetch_tile(sbase, 0, b, 0, t, coord);
    CP_COMMIT();

    for (int kt = 0; kt < NN / KT; kt++) {
        const int buf = kt & 1;
        __syncthreads();
        if (kt + 1 < NN / KT) {
            prefetch_tile(sbase, buf ^ 1, b, (kt + 1) * KT, t, coord);
            CP_COMMIT();
            CP_WAIT(1);
        } else {
            CP_WAIT(0);
        }
        __syncthreads();

        const float* ckb = (const float*)(s_raw + buf * BUFSZ + OFF_CK);
        const float* fdb = (const float*)(s_raw + buf * BUFSZ + OFF_FD);
        const uint32_t hhi = sbase + buf * BUFSZ + OFF_HHI;
        const uint32_t hlo = sbase + buf * BUFSZ + OFF_HLO;

        // ---- A fragments: 4 k-chunks of 16; lane keys {2t4,2t4+1,2t4+8,2t4+9}
        uint32_t ahi[4][4], alo[4][4];
#pragma unroll
        for (int kc = 0; kc < 4; kc++) {
            const int kb = kc * 16 + 2 * t4;
            float pv[2][4];   // [row][key: e0,o0,e1,o1]
#pragma unroll
            for (int kk = 0; kk < 4; kk++) {
                int j = kb + (kk >> 1) * 8 + (kk & 1);
                float kx = ckb[j * 4], ky = ckb[j * 4 + 1], kz = ckb[j * 4 + 2];
                float fd = fdb[j];
                pv[0][kk] = pcalc(fs0, M0, c0x, c0y, c0z, kx, ky, kz, fd);
                pv[1][kk] = pcalc(fs1, M1, c1x, c1y, c1z, kx, ky, kz, fd);
            }
            lsum0 += pv[0][0] + pv[0][1] + pv[0][2] + pv[0][3];
            lsum1 += pv[1][0] + pv[1][1] + pv[1][2] + pv[1][3];
            // hi packs: a0={r0:e0,o0} a1={r1:e0,o0} a2={r0:e1,o1} a3={r1:e1,o1}
#pragma unroll
            for (int rr = 0; rr < 2; rr++) {
#pragma unroll
                for (int hh = 0; hh < 2; hh++) {
                    float pe = pv[rr][hh * 2], po = pv[rr][hh * 2 + 1];
                    uint32_t hp = bfpack(po, pe);
                    float re = pe - __uint_as_float(hp << 16);
                    float ro = po - __uint_as_float(hp & 0xffff0000u);
                    ahi[kc][hh * 2 + rr] = hp;
                    alo[kc][hh * 2 + rr] = bfpack(ro, re);
                }
            }
        }

        // ---- MMA sweep: 8 nt-pairs x 4 kc; 2 LDSM.x4 + 6 MMA each ----
#pragma unroll
        for (int ntp = 0; ntp < 8; ntp++) {
#pragma unroll
            for (int kc = 0; kc < 4; kc++) {
                uint32_t base = (uint32_t)(kc * 16 * HROW + ntp * 32) + loff;
                uint32_t bh0, bh1, bh2, bh3, bl0, bl1, bl2, bl3;
                LDSM4T(bh0, bh1, bh2, bh3, hhi + base);
                LDSM4T(bl0, bl1, bl2, bl3, hlo + base);
                MMA_BF16(acc[2 * ntp],     ahi[kc], bh0, bh1);
                MMA_BF16(acc[2 * ntp],     ahi[kc], bl0, bl1);
                MMA_BF16(acc[2 * ntp],     alo[kc], bh0, bh1);
                MMA_BF16(acc[2 * ntp + 1], ahi[kc], bh2, bh3);
                MMA_BF16(acc[2 * ntp + 1], ahi[kc], bl2, bl3);
                MMA_BF16(acc[2 * ntp + 1], alo[kc], bh2, bh3);
            }
        }
    }

    // ---- row sums: quad all-reduce over t4 ----
    lsum0 += __shfl_xor_sync(0xffffffffu, lsum0, 1);
    lsum0 += __shfl_xor_sync(0xffffffffu, lsum0, 2);
    lsum1 += __shfl_xor_sync(0xffffffffu, lsum1, 1);
    lsum1 += __shfl_xor_sync(0xffffffffu, lsum1, 2);
    const float inv0 = 1.f / lsum0;
    const float inv1 = 1.f / lsum1;

    // ---- epilogue: normalize, ELU, store ----
    float* o0 = out + ((size_t)b * NN + row0) * FOUT;
    float* o1 = out + ((size_t)b * NN + row1) * FOUT;
#pragma unroll
    for (int nt = 0; nt < 16; nt++) {
        float v0 = acc[nt][0] * inv0, v1 = acc[nt][1] * inv0;
        float v2 = acc[nt][2] * inv1, v3 = acc[nt][3] * inv1;
        v0 = v0 > 0.f ? v0 : (__expf(v0) - 1.f);
        v1 = v1 > 0.f ? v1 : (__expf(v1) - 1.f);
        v2 = v2 > 0.f ? v2 : (__expf(v2) - 1.f);
        v3 = v3 > 0.f ? v3 : (__expf(v3) - 1.f);
        int col = nt * 8 + 2 * t4;
        *(float2*)(o0 + col) = make_float2(v0, v1);
        *(float2*)(o1 + col) = make_float2(v2, v3);
    }
}

// ---------------------------------------------------------------------------
extern "C" void kernel_launch(void* const* d_in, const int* in_sizes, int n_in,
                              void* d_out, int out_size) {
    const float *x = nullptr, *coord = nullptr, *W = nullptr, *a = nullptr;
    for (int i = 0; i < n_in; i++) {
        switch (in_sizes[i]) {
            case BB * NN * FIN: x     = (const float*)d_in[i]; break;
            case BB * NN * 3:   coord = (const float*)d_in[i]; break;
            case FIN * FOUT:    W     = (const float*)d_in[i]; break;
            case 2 * FOUT:      a     = (const float*)d_in[i]; break;
            default: break;
        }
    }
    float* out = (float*)d_out;

    gemm_h_kernel<<<(BB * NN) / 64, 256>>>(x, W, a);
    fdmax_kernel<<<BB, 256>>>();

    static bool attr_set = false;
    if (!attr_set) {
        cudaFuncSetAttribute(attn_kernel,
                             cudaFuncAttributeMaxDynamicSharedMemorySize, SM_TOTAL);
        attr_set = true;
    }
    attn_kernel<<<BB * (NN / MT), 256, SM_TOTAL>>>(coord, out);
}